// round 3
// baseline (speedup 1.0000x reference)
#include <cuda_runtime.h>

// Problem constants
#define BATCH 4
#define SEQ   2048
#define CH    1024
#define HEADS 16
#define HD    64
#define MTOT  (BATCH * SEQ)   // 8192
#define SCALE 0.125f          // HD^-0.5

// Scratch (allocation-free: __device__ globals)
__device__ float g_q[BATCH * HEADS * SEQ * HD];   // [bh][n][hd]
__device__ float g_k[BATCH * HEADS * SEQ * HD];
__device__ float g_v[BATCH * HEADS * SEQ * HD];
__device__ float g_ao[BATCH * SEQ * CH];          // attention output [b*N+n][c]

// ----------------------------------------------------------------------------
// Kernel 1: QKV projection.  out[m][d] = sum_c X[m][c] * W[d][c]
// M=8192, Nd=3072, K=1024.  Tile 64x64x16, 256 threads, 4x4 microtile.
// Epilogue scatters into g_q/g_k/g_v with [b*H+h][n][hd] layout.
// ----------------------------------------------------------------------------
__global__ __launch_bounds__(256) void qkv_gemm(const float* __restrict__ X,
                                                const float* __restrict__ W) {
    __shared__ float Xs[64 * 17];
    __shared__ float Ws[64 * 17];

    const int tid = threadIdx.x;
    const int ty = tid >> 4, tx = tid & 15;
    const int m0 = blockIdx.y * 64;
    const int n0 = blockIdx.x * 64;

    const int lr = tid >> 2;          // 0..63
    const int lc = (tid & 3) << 2;    // 0,4,8,12

    float acc[4][4] = {};

    for (int k0 = 0; k0 < 1024; k0 += 16) {
        __syncthreads();
        float4 xa = *(const float4*)(X + (size_t)(m0 + lr) * 1024 + k0 + lc);
        float4 wa = *(const float4*)(W + (size_t)(n0 + lr) * 1024 + k0 + lc);
        float* xp = Xs + lr * 17 + lc;
        xp[0] = xa.x; xp[1] = xa.y; xp[2] = xa.z; xp[3] = xa.w;
        float* wp = Ws + lr * 17 + lc;
        wp[0] = wa.x; wp[1] = wa.y; wp[2] = wa.z; wp[3] = wa.w;
        __syncthreads();

#pragma unroll
        for (int kk = 0; kk < 16; kk++) {
            float a[4], b[4];
#pragma unroll
            for (int i = 0; i < 4; i++) a[i] = Xs[(4 * ty + i) * 17 + kk];
#pragma unroll
            for (int j = 0; j < 4; j++) b[j] = Ws[(4 * tx + j) * 17 + kk];
#pragma unroll
            for (int i = 0; i < 4; i++)
#pragma unroll
                for (int j = 0; j < 4; j++) acc[i][j] += a[i] * b[j];
        }
    }

    // Scatter: d = n0 + 4*tx + j ;  d -> (three, h, hd). n0 multiple of 64 so
    // the whole 64-wide tile lies in one (three, h).
    const int three = n0 >> 10;
    const int h = (n0 >> 6) & 15;
    float* dst = (three == 0) ? g_q : (three == 1) ? g_k : g_v;
#pragma unroll
    for (int i = 0; i < 4; i++) {
        int m = m0 + 4 * ty + i;
        int b_ = m >> 11;          // /2048
        int n_ = m & 2047;
        float4 v4 = make_float4(acc[i][0], acc[i][1], acc[i][2], acc[i][3]);
        *(float4*)(dst + (size_t)((b_ * 16 + h) * 2048 + n_) * 64 + 4 * tx) = v4;
    }
}

// ----------------------------------------------------------------------------
// Kernel 2: flash attention.  One block per (b,h, 64-query tile).
// BM=BN=64, online softmax, bias[k] = mWin[b,k]*100 - 100 (key-only).
// P is staged into the K smem buffer for the PV pass.
// ----------------------------------------------------------------------------
__global__ __launch_bounds__(256) void attn_kernel(const float* __restrict__ mWin) {
    extern __shared__ float sm[];
    float* Qs     = sm;            // [64][65]  (Q * SCALE)
    float* Ks     = sm + 4160;     // [64][65]  (K tile, then P tile)
    float* Vs     = sm + 8320;     // [64][64]
    float* bias_s = sm + 12416;    // [64]

    const int tid = threadIdx.x;
    const int ty = tid >> 4, tx = tid & 15;
    const int qt = blockIdx.x & 31;     // query tile 0..31
    const int bh = blockIdx.x >> 5;     // 0..63
    const int b  = bh >> 4;
    const int h  = bh & 15;

    const float* qg  = g_q + (size_t)(bh * 2048 + qt * 64) * 64;
    const float* kg0 = g_k + (size_t)bh * 2048 * 64;
    const float* vg0 = g_v + (size_t)bh * 2048 * 64;

    // Stage Q (scaled) with pad-65 rows
    for (int i = tid; i < 1024; i += 256) {
        int r = i >> 4, c = (i & 15) << 2;
        float4 v = *(const float4*)(qg + r * 64 + c);
        float* p = Qs + r * 65 + c;
        p[0] = v.x * SCALE; p[1] = v.y * SCALE; p[2] = v.z * SCALE; p[3] = v.w * SCALE;
    }

    float acc[4][4] = {};
    float mrow[4] = {-1e30f, -1e30f, -1e30f, -1e30f};
    float lrow[4] = {};

    for (int kt = 0; kt < 32; kt++) {
        __syncthreads();   // prior PV reads (and Q staging, iter 0) complete

        const float* kg = kg0 + kt * 64 * 64;
        const float* vg = vg0 + kt * 64 * 64;
        for (int i = tid; i < 1024; i += 256) {
            int r = i >> 4, c = (i & 15) << 2;
            float4 v = *(const float4*)(kg + r * 64 + c);
            float* p = Ks + r * 65 + c;
            p[0] = v.x; p[1] = v.y; p[2] = v.z; p[3] = v.w;
            *(float4*)(Vs + r * 64 + c) = *(const float4*)(vg + r * 64 + c);
        }
        if (tid < 64) bias_s[tid] = mWin[b * 2048 + kt * 64 + tid] * 100.0f - 100.0f;
        __syncthreads();

        // S = (Q*SCALE) K^T  (64x64x64)
        float s[4][4] = {};
#pragma unroll 8
        for (int d = 0; d < 64; d++) {
            float a[4], kv[4];
#pragma unroll
            for (int i = 0; i < 4; i++) a[i] = Qs[(4 * ty + i) * 65 + d];
#pragma unroll
            for (int j = 0; j < 4; j++) kv[j] = Ks[(4 * tx + j) * 65 + d];
#pragma unroll
            for (int i = 0; i < 4; i++)
#pragma unroll
                for (int j = 0; j < 4; j++) s[i][j] += a[i] * kv[j];
        }

        float bj[4];
#pragma unroll
        for (int j = 0; j < 4; j++) bj[j] = bias_s[4 * tx + j];
#pragma unroll
        for (int i = 0; i < 4; i++)
#pragma unroll
            for (int j = 0; j < 4; j++) s[i][j] += bj[j];

        // Online softmax per row (rows owned by ty-group; reduce across 16 tx lanes)
#pragma unroll
        for (int i = 0; i < 4; i++) {
            float mloc = fmaxf(fmaxf(s[i][0], s[i][1]), fmaxf(s[i][2], s[i][3]));
#pragma unroll
            for (int off = 8; off >= 1; off >>= 1)
                mloc = fmaxf(mloc, __shfl_xor_sync(0xffffffffu, mloc, off));
            float mnew = fmaxf(mrow[i], mloc);
            float corr = __expf(mrow[i] - mnew);
            float ls = 0.0f;
#pragma unroll
            for (int j = 0; j < 4; j++) {
                s[i][j] = __expf(s[i][j] - mnew);
                ls += s[i][j];
            }
#pragma unroll
            for (int off = 8; off >= 1; off >>= 1)
                ls += __shfl_xor_sync(0xffffffffu, ls, off);
            lrow[i] = lrow[i] * corr + ls;
            mrow[i] = mnew;
#pragma unroll
            for (int j = 0; j < 4; j++) acc[i][j] *= corr;
        }

        __syncthreads();   // everyone done reading Ks as K
        // Stage P into Ks buffer: Ps[row][key], stride 65
#pragma unroll
        for (int i = 0; i < 4; i++)
#pragma unroll
            for (int j = 0; j < 4; j++)
                Ks[(4 * ty + i) * 65 + 4 * tx + j] = s[i][j];
        __syncthreads();

        // O += P V  (64x64x64)
#pragma unroll 8
        for (int k = 0; k < 64; k++) {
            float pv[4], vv[4];
#pragma unroll
            for (int i = 0; i < 4; i++) pv[i] = Ks[(4 * ty + i) * 65 + k];
#pragma unroll
            for (int j = 0; j < 4; j++) vv[j] = Vs[k * 64 + 4 * tx + j];
#pragma unroll
            for (int i = 0; i < 4; i++)
#pragma unroll
                for (int j = 0; j < 4; j++) acc[i][j] += pv[i] * vv[j];
        }
    }

    // Epilogue: divide by l, write [b*N+n][h*64+hd]
    const int qbase = b * 2048 + qt * 64;
#pragma unroll
    for (int i = 0; i < 4; i++) {
        float inv = 1.0f / lrow[i];
        float4 o = make_float4(acc[i][0] * inv, acc[i][1] * inv,
                               acc[i][2] * inv, acc[i][3] * inv);
        *(float4*)(g_ao + (size_t)(qbase + 4 * ty + i) * 1024 + h * 64 + 4 * tx) = o;
    }
}

// ----------------------------------------------------------------------------
// Kernel 3: output projection.  out[m][d] = sum_c g_ao[m][c]*Wp[d][c] + bias[d]
// ----------------------------------------------------------------------------
__global__ __launch_bounds__(256) void proj_gemm(const float* __restrict__ W,
                                                 const float* __restrict__ bias,
                                                 float* __restrict__ out) {
    __shared__ float Xs[64 * 17];
    __shared__ float Ws[64 * 17];

    const int tid = threadIdx.x;
    const int ty = tid >> 4, tx = tid & 15;
    const int m0 = blockIdx.y * 64;
    const int n0 = blockIdx.x * 64;

    const int lr = tid >> 2;
    const int lc = (tid & 3) << 2;

    float acc[4][4] = {};

    for (int k0 = 0; k0 < 1024; k0 += 16) {
        __syncthreads();
        float4 xa = *(const float4*)(g_ao + (size_t)(m0 + lr) * 1024 + k0 + lc);
        float4 wa = *(const float4*)(W + (size_t)(n0 + lr) * 1024 + k0 + lc);
        float* xp = Xs + lr * 17 + lc;
        xp[0] = xa.x; xp[1] = xa.y; xp[2] = xa.z; xp[3] = xa.w;
        float* wp = Ws + lr * 17 + lc;
        wp[0] = wa.x; wp[1] = wa.y; wp[2] = wa.z; wp[3] = wa.w;
        __syncthreads();

#pragma unroll
        for (int kk = 0; kk < 16; kk++) {
            float a[4], b[4];
#pragma unroll
            for (int i = 0; i < 4; i++) a[i] = Xs[(4 * ty + i) * 17 + kk];
#pragma unroll
            for (int j = 0; j < 4; j++) b[j] = Ws[(4 * tx + j) * 17 + kk];
#pragma unroll
            for (int i = 0; i < 4; i++)
#pragma unroll
                for (int j = 0; j < 4; j++) acc[i][j] += a[i] * b[j];
        }
    }

    float4 bv = *(const float4*)(bias + n0 + 4 * tx);
#pragma unroll
    for (int i = 0; i < 4; i++) {
        int m = m0 + 4 * ty + i;
        float4 o = make_float4(acc[i][0] + bv.x, acc[i][1] + bv.y,
                               acc[i][2] + bv.z, acc[i][3] + bv.w);
        *(float4*)(out + (size_t)m * 1024 + n0 + 4 * tx) = o;
    }
}

// ----------------------------------------------------------------------------
extern "C" void kernel_launch(void* const* d_in, const int* in_sizes, int n_in,
                              void* d_out, int out_size) {
    const float* x      = (const float*)d_in[0];
    const float* mWin   = (const float*)d_in[1];
    const float* w_qkv  = (const float*)d_in[2];
    const float* w_proj = (const float*)d_in[3];
    const float* b_proj = (const float*)d_in[4];
    float* out = (float*)d_out;

    const int ATTN_SMEM = 49920;  // (4160+4160+4096+64) floats
    cudaFuncSetAttribute(attn_kernel, cudaFuncAttributeMaxDynamicSharedMemorySize,
                         ATTN_SMEM);

    qkv_gemm<<<dim3(48, 128), 256>>>(x, w_qkv);
    attn_kernel<<<2048, 256, ATTN_SMEM>>>(mWin);
    proj_gemm<<<dim3(16, 128), 256>>>(w_proj, b_proj, out);
}

// round 6
// speedup vs baseline: 1.4359x; 1.4359x over previous
#include <cuda_runtime.h>
#include <cuda_bf16.h>
#include <cstdint>

// Problem constants
#define BATCH 4
#define SEQ   2048
#define CH    1024
#define HEADS 16
#define HD    64
#define SCALE 0.125f

// ---------------------------------------------------------------------------
// Scratch (allocation-free: __device__ globals)
// ---------------------------------------------------------------------------
__device__ __align__(16) float g_q[BATCH * HEADS * SEQ * HD];
__device__ __align__(16) float g_k[BATCH * HEADS * SEQ * HD];
__device__ __align__(16) float g_v[BATCH * HEADS * SEQ * HD];
__device__ __align__(16) float g_ao[BATCH * SEQ * CH];

__device__ __align__(16) __nv_bfloat16 g_xhi[8192 * 1024];
__device__ __align__(16) __nv_bfloat16 g_xlo[8192 * 1024];
__device__ __align__(16) __nv_bfloat16 g_wqh[3072 * 1024];
__device__ __align__(16) __nv_bfloat16 g_wql[3072 * 1024];
__device__ __align__(16) __nv_bfloat16 g_wph[1024 * 1024];
__device__ __align__(16) __nv_bfloat16 g_wpl[1024 * 1024];
__device__ __align__(16) __nv_bfloat16 g_aoh[8192 * 1024];
__device__ __align__(16) __nv_bfloat16 g_aol[8192 * 1024];

// ---------------------------------------------------------------------------
// Warp-MMA helpers (portable sm_80+ path; tcgen05 is rejected by the
// harness's plain sm_100 ptxas target)
// ---------------------------------------------------------------------------
__device__ __forceinline__ uint32_t smem_u32(const void* p) {
    uint32_t a;
    asm("{ .reg .u64 t; cvta.to.shared.u64 t, %1; cvt.u32.u64 %0, t; }"
        : "=r"(a) : "l"(p));
    return a;
}

__device__ __forceinline__ void ldsm_x4(uint32_t addr, uint32_t& r0, uint32_t& r1,
                                        uint32_t& r2, uint32_t& r3) {
    asm volatile("ldmatrix.sync.aligned.m8n8.x4.shared.b16 {%0,%1,%2,%3}, [%4];"
                 : "=r"(r0), "=r"(r1), "=r"(r2), "=r"(r3) : "r"(addr));
}

__device__ __forceinline__ void mma_bf16(float* d, const uint32_t* a,
                                         const uint32_t* b) {
    asm volatile(
        "mma.sync.aligned.m16n8k16.row.col.f32.bf16.bf16.f32 "
        "{%0,%1,%2,%3}, {%4,%5,%6,%7}, {%8,%9}, {%0,%1,%2,%3};"
        : "+f"(d[0]), "+f"(d[1]), "+f"(d[2]), "+f"(d[3])
        : "r"(a[0]), "r"(a[1]), "r"(a[2]), "r"(a[3]), "r"(b[0]), "r"(b[1]));
}

// ---------------------------------------------------------------------------
// fp32 -> (bf16 hi, bf16 lo) split conversion. One float4 per thread.
// ---------------------------------------------------------------------------
__global__ __launch_bounds__(256) void split_kernel(const float* __restrict__ src,
                                                    __nv_bfloat16* __restrict__ hi,
                                                    __nv_bfloat16* __restrict__ lo) {
    int i = blockIdx.x * 256 + threadIdx.x;
    float4 v = ((const float4*)src)[i];
    __nv_bfloat16 h0 = __float2bfloat16(v.x);
    __nv_bfloat16 h1 = __float2bfloat16(v.y);
    __nv_bfloat16 h2 = __float2bfloat16(v.z);
    __nv_bfloat16 h3 = __float2bfloat16(v.w);
    __nv_bfloat16 l0 = __float2bfloat16(v.x - __bfloat162float(h0));
    __nv_bfloat16 l1 = __float2bfloat16(v.y - __bfloat162float(h1));
    __nv_bfloat16 l2 = __float2bfloat16(v.z - __bfloat162float(h2));
    __nv_bfloat16 l3 = __float2bfloat16(v.w - __bfloat162float(h3));
    ((__nv_bfloat162*)hi)[2 * i]     = __nv_bfloat162(h0, h1);
    ((__nv_bfloat162*)hi)[2 * i + 1] = __nv_bfloat162(h2, h3);
    ((__nv_bfloat162*)lo)[2 * i]     = __nv_bfloat162(l0, l1);
    ((__nv_bfloat162*)lo)[2 * i + 1] = __nv_bfloat162(l2, l3);
}

// ---------------------------------------------------------------------------
// mma.sync GEMM: D[M,Nd] = A[M,1024] * B[Nd,1024]^T, bf16 3-term split,
// fp32 register accumulators held across all 3 passes.
// Block tile 128x128, 8 warps (2x4), warp tile 64x32, K chunk 32.
// mode 0: scatter to g_q/g_k/g_v.  mode 1: out = D + bias.
// ---------------------------------------------------------------------------
#define LDS 40   // padded smem row stride (bf16 elems): conflict-free ldmatrix

__global__ __launch_bounds__(256) void gemm_mma(
    const __nv_bfloat16* __restrict__ Ahi, const __nv_bfloat16* __restrict__ Alo,
    const __nv_bfloat16* __restrict__ Bhi, const __nv_bfloat16* __restrict__ Blo,
    const float* __restrict__ bias, float* __restrict__ out, int mode) {
    __shared__ __align__(16) __nv_bfloat16 As[128 * LDS];
    __shared__ __align__(16) __nv_bfloat16 Bs[128 * LDS];

    const int tid = threadIdx.x;
    const int wid = tid >> 5, lane = tid & 31;
    const int m0 = blockIdx.y * 128;
    const int n0 = blockIdx.x * 128;
    const int wm = (wid >> 2) * 64;       // warp M offset in tile
    const int wn = (wid & 3) * 32;        // warp N offset in tile

    const int lrow = tid >> 2;            // 0..63
    const int lcol = (tid & 3) * 8;       // 0,8,16,24

    float acc[4][4][4] = {};              // [mi][nj][reg]

    const __nv_bfloat16* Aps[3] = {Ahi, Ahi, Alo};
    const __nv_bfloat16* Bps[3] = {Bhi, Blo, Bhi};

    // ldmatrix source addresses (byte, shared space)
    uint32_t as_base = smem_u32(As);
    uint32_t bs_base = smem_u32(Bs);
    uint32_t a_addr[4], b_addr[2];
#pragma unroll
    for (int i = 0; i < 4; i++)
        a_addr[i] = as_base +
            ((wm + i * 16 + (lane & 15)) * LDS + ((lane >> 4) << 3)) * 2;
#pragma unroll
    for (int p = 0; p < 2; p++)
        b_addr[p] = bs_base +
            ((wn + p * 16 + ((lane >> 4) << 3) + (lane & 7)) * LDS +
             (((lane >> 3) & 1) << 3)) * 2;

    // Prefetch chunk 0
    uint4 pa0 = *(const uint4*)(Aps[0] + (size_t)(m0 + lrow) * 1024 + lcol);
    uint4 pa1 = *(const uint4*)(Aps[0] + (size_t)(m0 + lrow + 64) * 1024 + lcol);
    uint4 pb0 = *(const uint4*)(Bps[0] + (size_t)(n0 + lrow) * 1024 + lcol);
    uint4 pb1 = *(const uint4*)(Bps[0] + (size_t)(n0 + lrow + 64) * 1024 + lcol);

    for (int c = 0; c < 96; c++) {
        *(uint4*)&As[lrow * LDS + lcol] = pa0;
        *(uint4*)&As[(lrow + 64) * LDS + lcol] = pa1;
        *(uint4*)&Bs[lrow * LDS + lcol] = pb0;
        *(uint4*)&Bs[(lrow + 64) * LDS + lcol] = pb1;
        __syncthreads();

        if (c + 1 < 96) {
            int cn = c + 1;
            int pass = cn >> 5;
            int k0 = (cn & 31) * 32;
            const __nv_bfloat16* Ap = Aps[pass];
            const __nv_bfloat16* Bp = Bps[pass];
            pa0 = *(const uint4*)(Ap + (size_t)(m0 + lrow) * 1024 + k0 + lcol);
            pa1 = *(const uint4*)(Ap + (size_t)(m0 + lrow + 64) * 1024 + k0 + lcol);
            pb0 = *(const uint4*)(Bp + (size_t)(n0 + lrow) * 1024 + k0 + lcol);
            pb1 = *(const uint4*)(Bp + (size_t)(n0 + lrow + 64) * 1024 + k0 + lcol);
        }

#pragma unroll
        for (int kk = 0; kk < 2; kk++) {
            uint32_t a[4][4], b[2][4];
#pragma unroll
            for (int i = 0; i < 4; i++)
                ldsm_x4(a_addr[i] + kk * 32, a[i][0], a[i][1], a[i][2], a[i][3]);
#pragma unroll
            for (int p = 0; p < 2; p++)
                ldsm_x4(b_addr[p] + kk * 32, b[p][0], b[p][1], b[p][2], b[p][3]);
#pragma unroll
            for (int i = 0; i < 4; i++)
#pragma unroll
                for (int j = 0; j < 4; j++)
                    mma_bf16(acc[i][j], a[i], &b[j >> 1][(j & 1) * 2]);
        }
        __syncthreads();
    }

    // Epilogue: direct fragment stores (float2)
    const int rl = lane >> 2;             // 0..7
    const int cl = (lane & 3) * 2;        // 0,2,4,6
#pragma unroll
    for (int i = 0; i < 4; i++) {
#pragma unroll
        for (int j = 0; j < 4; j++) {
#pragma unroll
            for (int pr = 0; pr < 2; pr++) {
                int r  = m0 + wm + i * 16 + rl + pr * 8;
                int cg = n0 + wn + j * 8 + cl;
                float2 v = make_float2(acc[i][j][pr * 2], acc[i][j][pr * 2 + 1]);
                if (mode == 0) {
                    int three = cg >> 10;
                    int h = (cg >> 6) & 15;
                    int hd = cg & 63;
                    int b_ = r >> 11, nn = r & 2047;
                    float* dst = (three == 0) ? g_q : (three == 1) ? g_k : g_v;
                    *(float2*)(dst + (size_t)((b_ * 16 + h) * 2048 + nn) * 64 + hd) = v;
                } else {
                    v.x += bias[cg];
                    v.y += bias[cg + 1];
                    *(float2*)(out + (size_t)r * 1024 + cg) = v;
                }
            }
        }
    }
}

// ---------------------------------------------------------------------------
// Flash attention (unchanged, verified): one block per (b,h,64-query tile).
// ---------------------------------------------------------------------------
__global__ __launch_bounds__(256) void attn_kernel(const float* __restrict__ mWin) {
    extern __shared__ float sm[];
    float* Qs     = sm;
    float* Ks     = sm + 4160;
    float* Vs     = sm + 8320;
    float* bias_s = sm + 12416;

    const int tid = threadIdx.x;
    const int ty = tid >> 4, tx = tid & 15;
    const int qt = blockIdx.x & 31;
    const int bh = blockIdx.x >> 5;
    const int b  = bh >> 4;
    const int h  = bh & 15;

    const float* qg  = g_q + (size_t)(bh * 2048 + qt * 64) * 64;
    const float* kg0 = g_k + (size_t)bh * 2048 * 64;
    const float* vg0 = g_v + (size_t)bh * 2048 * 64;

    for (int i = tid; i < 1024; i += 256) {
        int r = i >> 4, cI = (i & 15) << 2;
        float4 v = *(const float4*)(qg + r * 64 + cI);
        float* p = Qs + r * 65 + cI;
        p[0] = v.x * SCALE; p[1] = v.y * SCALE; p[2] = v.z * SCALE; p[3] = v.w * SCALE;
    }

    float acc[4][4] = {};
    float mrow[4] = {-1e30f, -1e30f, -1e30f, -1e30f};
    float lrow[4] = {};

    for (int kt = 0; kt < 32; kt++) {
        __syncthreads();
        const float* kg = kg0 + kt * 64 * 64;
        const float* vg = vg0 + kt * 64 * 64;
        for (int i = tid; i < 1024; i += 256) {
            int r = i >> 4, cI = (i & 15) << 2;
            float4 v = *(const float4*)(kg + r * 64 + cI);
            float* p = Ks + r * 65 + cI;
            p[0] = v.x; p[1] = v.y; p[2] = v.z; p[3] = v.w;
            *(float4*)(Vs + r * 64 + cI) = *(const float4*)(vg + r * 64 + cI);
        }
        if (tid < 64) bias_s[tid] = mWin[b * 2048 + kt * 64 + tid] * 100.0f - 100.0f;
        __syncthreads();

        float s[4][4] = {};
#pragma unroll 8
        for (int d = 0; d < 64; d++) {
            float a[4], kv[4];
#pragma unroll
            for (int i = 0; i < 4; i++) a[i] = Qs[(4 * ty + i) * 65 + d];
#pragma unroll
            for (int j = 0; j < 4; j++) kv[j] = Ks[(4 * tx + j) * 65 + d];
#pragma unroll
            for (int i = 0; i < 4; i++)
#pragma unroll
                for (int j = 0; j < 4; j++) s[i][j] += a[i] * kv[j];
        }

        float bj[4];
#pragma unroll
        for (int j = 0; j < 4; j++) bj[j] = bias_s[4 * tx + j];
#pragma unroll
        for (int i = 0; i < 4; i++)
#pragma unroll
            for (int j = 0; j < 4; j++) s[i][j] += bj[j];

#pragma unroll
        for (int i = 0; i < 4; i++) {
            float mloc = fmaxf(fmaxf(s[i][0], s[i][1]), fmaxf(s[i][2], s[i][3]));
#pragma unroll
            for (int off = 8; off >= 1; off >>= 1)
                mloc = fmaxf(mloc, __shfl_xor_sync(0xffffffffu, mloc, off));
            float mnew = fmaxf(mrow[i], mloc);
            float corr = __expf(mrow[i] - mnew);
            float ls = 0.0f;
#pragma unroll
            for (int j = 0; j < 4; j++) {
                s[i][j] = __expf(s[i][j] - mnew);
                ls += s[i][j];
            }
#pragma unroll
            for (int off = 8; off >= 1; off >>= 1)
                ls += __shfl_xor_sync(0xffffffffu, ls, off);
            lrow[i] = lrow[i] * corr + ls;
            mrow[i] = mnew;
#pragma unroll
            for (int j = 0; j < 4; j++) acc[i][j] *= corr;
        }

        __syncthreads();
#pragma unroll
        for (int i = 0; i < 4; i++)
#pragma unroll
            for (int j = 0; j < 4; j++)
                Ks[(4 * ty + i) * 65 + 4 * tx + j] = s[i][j];
        __syncthreads();

#pragma unroll 8
        for (int k = 0; k < 64; k++) {
            float pv[4], vv[4];
#pragma unroll
            for (int i = 0; i < 4; i++) pv[i] = Ks[(4 * ty + i) * 65 + k];
#pragma unroll
            for (int j = 0; j < 4; j++) vv[j] = Vs[k * 64 + 4 * tx + j];
#pragma unroll
            for (int i = 0; i < 4; i++)
#pragma unroll
                for (int j = 0; j < 4; j++) acc[i][j] += pv[i] * vv[j];
        }
    }

    const int qbase = b * 2048 + qt * 64;
#pragma unroll
    for (int i = 0; i < 4; i++) {
        float inv = 1.0f / lrow[i];
        float4 o = make_float4(acc[i][0] * inv, acc[i][1] * inv,
                               acc[i][2] * inv, acc[i][3] * inv);
        *(float4*)(g_ao + (size_t)(qbase + 4 * ty + i) * 1024 + h * 64 + 4 * tx) = o;
    }
}

// ---------------------------------------------------------------------------
extern "C" void kernel_launch(void* const* d_in, const int* in_sizes, int n_in,
                              void* d_out, int out_size) {
    const float* x      = (const float*)d_in[0];
    const float* mWin   = (const float*)d_in[1];
    const float* w_qkv  = (const float*)d_in[2];
    const float* w_proj = (const float*)d_in[3];
    const float* b_proj = (const float*)d_in[4];
    float* out = (float*)d_out;

    __nv_bfloat16 *xhi, *xlo, *wqh, *wql, *wph, *wpl, *aoh, *aol;
    cudaGetSymbolAddress((void**)&xhi, g_xhi);
    cudaGetSymbolAddress((void**)&xlo, g_xlo);
    cudaGetSymbolAddress((void**)&wqh, g_wqh);
    cudaGetSymbolAddress((void**)&wql, g_wql);
    cudaGetSymbolAddress((void**)&wph, g_wph);
    cudaGetSymbolAddress((void**)&wpl, g_wpl);
    cudaGetSymbolAddress((void**)&aoh, g_aoh);
    cudaGetSymbolAddress((void**)&aol, g_aol);
    float* ao;
    cudaGetSymbolAddress((void**)&ao, g_ao);

    const int ATTN_SMEM = 49920;
    cudaFuncSetAttribute(attn_kernel, cudaFuncAttributeMaxDynamicSharedMemorySize,
                         ATTN_SMEM);

    // Split conversions (fp32 -> bf16 hi/lo)
    split_kernel<<<8192, 256>>>(x, xhi, xlo);
    split_kernel<<<3072, 256>>>(w_qkv, wqh, wql);
    split_kernel<<<1024, 256>>>(w_proj, wph, wpl);

    // QKV projection (mma.sync bf16 split), scatter into g_q/g_k/g_v
    gemm_mma<<<dim3(24, 64), 256>>>(xhi, xlo, wqh, wql, nullptr, nullptr, 0);

    // Flash attention (fp32 SIMT)
    attn_kernel<<<2048, 256, ATTN_SMEM>>>(mWin);

    // Output projection (mma.sync bf16 split) + bias
    split_kernel<<<8192, 256>>>(ao, aoh, aol);
    gemm_mma<<<dim3(8, 64), 256>>>(aoh, aol, wph, wpl, b_proj, out, 1);
}

// round 8
// speedup vs baseline: 3.1488x; 2.1930x over previous
#include <cuda_runtime.h>
#include <cuda_bf16.h>
#include <cuda_fp16.h>
#include <cstdint>

// Problem constants
#define BATCH 4
#define SEQ   2048
#define CH    1024
#define HEADS 16
#define HD    64
#define QSCALE 0.18033688011112042f   // 0.125 * log2(e)
#define LOG2E  1.4426950408889634f

// ---------------------------------------------------------------------------
// Scratch (allocation-free: __device__ globals)
// ---------------------------------------------------------------------------
__device__ __align__(16) float g_ao[BATCH * SEQ * CH];

__device__ __align__(16) __half g_qh[BATCH * HEADS * SEQ * HD];
__device__ __align__(16) __half g_ql[BATCH * HEADS * SEQ * HD];
__device__ __align__(16) __half g_kf[BATCH * HEADS * SEQ * HD];
__device__ __align__(16) __half g_vf[BATCH * HEADS * SEQ * HD];

__device__ __align__(16) __nv_bfloat16 g_xhi[8192 * 1024];
__device__ __align__(16) __nv_bfloat16 g_xlo[8192 * 1024];
__device__ __align__(16) __nv_bfloat16 g_wqh[3072 * 1024];
__device__ __align__(16) __nv_bfloat16 g_wql[3072 * 1024];
__device__ __align__(16) __nv_bfloat16 g_wph[1024 * 1024];
__device__ __align__(16) __nv_bfloat16 g_wpl[1024 * 1024];
__device__ __align__(16) __nv_bfloat16 g_aoh[8192 * 1024];
__device__ __align__(16) __nv_bfloat16 g_aol[8192 * 1024];

// ---------------------------------------------------------------------------
// Warp-MMA helpers (portable sm_80+ path; tcgen05 rejected by sm_100 target)
// ---------------------------------------------------------------------------
__device__ __forceinline__ uint32_t smem_u32(const void* p) {
    uint32_t a;
    asm("{ .reg .u64 t; cvta.to.shared.u64 t, %1; cvt.u32.u64 %0, t; }"
        : "=r"(a) : "l"(p));
    return a;
}

__device__ __forceinline__ void ldsm_x4(uint32_t addr, uint32_t& r0, uint32_t& r1,
                                        uint32_t& r2, uint32_t& r3) {
    asm volatile("ldmatrix.sync.aligned.m8n8.x4.shared.b16 {%0,%1,%2,%3}, [%4];"
                 : "=r"(r0), "=r"(r1), "=r"(r2), "=r"(r3) : "r"(addr));
}

__device__ __forceinline__ void ldsm_x4_t(uint32_t addr, uint32_t& r0, uint32_t& r1,
                                          uint32_t& r2, uint32_t& r3) {
    asm volatile("ldmatrix.sync.aligned.m8n8.x4.trans.shared.b16 {%0,%1,%2,%3}, [%4];"
                 : "=r"(r0), "=r"(r1), "=r"(r2), "=r"(r3) : "r"(addr));
}

__device__ __forceinline__ void mma_bf16(float* d, const uint32_t* a,
                                         const uint32_t* b) {
    asm volatile(
        "mma.sync.aligned.m16n8k16.row.col.f32.bf16.bf16.f32 "
        "{%0,%1,%2,%3}, {%4,%5,%6,%7}, {%8,%9}, {%0,%1,%2,%3};"
        : "+f"(d[0]), "+f"(d[1]), "+f"(d[2]), "+f"(d[3])
        : "r"(a[0]), "r"(a[1]), "r"(a[2]), "r"(a[3]), "r"(b[0]), "r"(b[1]));
}

__device__ __forceinline__ void mma_f16(float* d, const uint32_t* a,
                                        const uint32_t* b) {
    asm volatile(
        "mma.sync.aligned.m16n8k16.row.col.f32.f16.f16.f32 "
        "{%0,%1,%2,%3}, {%4,%5,%6,%7}, {%8,%9}, {%0,%1,%2,%3};"
        : "+f"(d[0]), "+f"(d[1]), "+f"(d[2]), "+f"(d[3])
        : "r"(a[0]), "r"(a[1]), "r"(a[2]), "r"(a[3]), "r"(b[0]), "r"(b[1]));
}

__device__ __forceinline__ void cp16(uint32_t dst, const void* src) {
    asm volatile("cp.async.cg.shared.global [%0], [%1], 16;"
                 :: "r"(dst), "l"(src));
}

__device__ __forceinline__ uint32_t pack_h2(float a, float b) {
    __half2 h = __floats2half2_rn(a, b);
    return *reinterpret_cast<uint32_t*>(&h);
}

// exp2 on FMA pipe: magic-number round + degree-5 Taylor. x <= 0 expected.
__device__ __forceinline__ float exp2_poly(float x) {
    x = fmaxf(x, -126.0f);
    float z = x + 12582912.0f;            // 1.5*2^23: RN rounds x to integer
    float r = z - 12582912.0f;            // r = rint(x)
    float f = x - r;                      // f in [-0.5, 0.5]
    float p = 1.3333558146e-3f;
    p = fmaf(p, f, 9.6181291076e-3f);
    p = fmaf(p, f, 5.5504108665e-2f);
    p = fmaf(p, f, 2.4022650696e-1f);
    p = fmaf(p, f, 6.9314718056e-1f);
    p = fmaf(p, f, 1.0f);
    int e = __float_as_int(z) - 0x4B400000;     // integer r from magic mantissa
    return p * __int_as_float((e + 127) << 23);
}

// ---------------------------------------------------------------------------
// fp32 -> (bf16 hi, bf16 lo) split conversion. One float4 per thread.
// ---------------------------------------------------------------------------
__global__ __launch_bounds__(256) void split_kernel(const float* __restrict__ src,
                                                    __nv_bfloat16* __restrict__ hi,
                                                    __nv_bfloat16* __restrict__ lo) {
    int i = blockIdx.x * 256 + threadIdx.x;
    float4 v = ((const float4*)src)[i];
    __nv_bfloat16 h0 = __float2bfloat16(v.x);
    __nv_bfloat16 h1 = __float2bfloat16(v.y);
    __nv_bfloat16 h2 = __float2bfloat16(v.z);
    __nv_bfloat16 h3 = __float2bfloat16(v.w);
    __nv_bfloat16 l0 = __float2bfloat16(v.x - __bfloat162float(h0));
    __nv_bfloat16 l1 = __float2bfloat16(v.y - __bfloat162float(h1));
    __nv_bfloat16 l2 = __float2bfloat16(v.z - __bfloat162float(h2));
    __nv_bfloat16 l3 = __float2bfloat16(v.w - __bfloat162float(h3));
    ((__nv_bfloat162*)hi)[2 * i]     = __nv_bfloat162(h0, h1);
    ((__nv_bfloat162*)hi)[2 * i + 1] = __nv_bfloat162(h2, h3);
    ((__nv_bfloat162*)lo)[2 * i]     = __nv_bfloat162(l0, l1);
    ((__nv_bfloat162*)lo)[2 * i + 1] = __nv_bfloat162(l2, l3);
}

// ---------------------------------------------------------------------------
// mma.sync GEMM (bf16 3-term split). Block 128x128, 8 warps, K chunk 32.
// mode 0: qkv -> write fp16 Qh/Ql (scaled), Kf, Vf.  mode 1: out = D + bias.
// ---------------------------------------------------------------------------
#define LDSG 40

__global__ __launch_bounds__(256) void gemm_mma(
    const __nv_bfloat16* __restrict__ Ahi, const __nv_bfloat16* __restrict__ Alo,
    const __nv_bfloat16* __restrict__ Bhi, const __nv_bfloat16* __restrict__ Blo,
    const float* __restrict__ bias, float* __restrict__ out, int mode) {
    __shared__ __align__(16) __nv_bfloat16 As[128 * LDSG];
    __shared__ __align__(16) __nv_bfloat16 Bs[128 * LDSG];

    const int tid = threadIdx.x;
    const int wid = tid >> 5, lane = tid & 31;
    const int m0 = blockIdx.y * 128;
    const int n0 = blockIdx.x * 128;
    const int wm = (wid >> 2) * 64;
    const int wn = (wid & 3) * 32;

    const int lrow = tid >> 2;
    const int lcol = (tid & 3) * 8;

    float acc[4][4][4] = {};

    const __nv_bfloat16* Aps[3] = {Ahi, Ahi, Alo};
    const __nv_bfloat16* Bps[3] = {Bhi, Blo, Bhi};

    uint32_t as_base = smem_u32(As);
    uint32_t bs_base = smem_u32(Bs);
    uint32_t a_addr[4], b_addr[2];
#pragma unroll
    for (int i = 0; i < 4; i++)
        a_addr[i] = as_base +
            ((wm + i * 16 + (lane & 15)) * LDSG + ((lane >> 4) << 3)) * 2;
#pragma unroll
    for (int p = 0; p < 2; p++)
        b_addr[p] = bs_base +
            ((wn + p * 16 + ((lane >> 4) << 3) + (lane & 7)) * LDSG +
             (((lane >> 3) & 1) << 3)) * 2;

    uint4 pa0 = *(const uint4*)(Aps[0] + (size_t)(m0 + lrow) * 1024 + lcol);
    uint4 pa1 = *(const uint4*)(Aps[0] + (size_t)(m0 + lrow + 64) * 1024 + lcol);
    uint4 pb0 = *(const uint4*)(Bps[0] + (size_t)(n0 + lrow) * 1024 + lcol);
    uint4 pb1 = *(const uint4*)(Bps[0] + (size_t)(n0 + lrow + 64) * 1024 + lcol);

    for (int c = 0; c < 96; c++) {
        *(uint4*)&As[lrow * LDSG + lcol] = pa0;
        *(uint4*)&As[(lrow + 64) * LDSG + lcol] = pa1;
        *(uint4*)&Bs[lrow * LDSG + lcol] = pb0;
        *(uint4*)&Bs[(lrow + 64) * LDSG + lcol] = pb1;
        __syncthreads();

        if (c + 1 < 96) {
            int cn = c + 1;
            int pass = cn >> 5;
            int k0 = (cn & 31) * 32;
            const __nv_bfloat16* Ap = Aps[pass];
            const __nv_bfloat16* Bp = Bps[pass];
            pa0 = *(const uint4*)(Ap + (size_t)(m0 + lrow) * 1024 + k0 + lcol);
            pa1 = *(const uint4*)(Ap + (size_t)(m0 + lrow + 64) * 1024 + k0 + lcol);
            pb0 = *(const uint4*)(Bp + (size_t)(n0 + lrow) * 1024 + k0 + lcol);
            pb1 = *(const uint4*)(Bp + (size_t)(n0 + lrow + 64) * 1024 + k0 + lcol);
        }

#pragma unroll
        for (int kk = 0; kk < 2; kk++) {
            uint32_t a[4][4], b[2][4];
#pragma unroll
            for (int i = 0; i < 4; i++)
                ldsm_x4(a_addr[i] + kk * 32, a[i][0], a[i][1], a[i][2], a[i][3]);
#pragma unroll
            for (int p = 0; p < 2; p++)
                ldsm_x4(b_addr[p] + kk * 32, b[p][0], b[p][1], b[p][2], b[p][3]);
#pragma unroll
            for (int i = 0; i < 4; i++)
#pragma unroll
                for (int j = 0; j < 4; j++)
                    mma_bf16(acc[i][j], a[i], &b[j >> 1][(j & 1) * 2]);
        }
        __syncthreads();
    }

    const int rl = lane >> 2;
    const int cl = (lane & 3) * 2;
#pragma unroll
    for (int i = 0; i < 4; i++) {
#pragma unroll
        for (int j = 0; j < 4; j++) {
#pragma unroll
            for (int pr = 0; pr < 2; pr++) {
                int r  = m0 + wm + i * 16 + rl + pr * 8;
                int cg = n0 + wn + j * 8 + cl;
                float2 v = make_float2(acc[i][j][pr * 2], acc[i][j][pr * 2 + 1]);
                if (mode == 0) {
                    int three = cg >> 10;
                    int h = (cg >> 6) & 15;
                    int hd = cg & 63;
                    int b_ = r >> 11, nn = r & 2047;
                    size_t off = (size_t)((b_ * 16 + h) * 2048 + nn) * 64 + hd;
                    if (three == 0) {
                        float sx = v.x * QSCALE, sy = v.y * QSCALE;
                        __half2 hh = __floats2half2_rn(sx, sy);
                        __half2 hl = __floats2half2_rn(sx - __low2float(hh),
                                                       sy - __high2float(hh));
                        *(__half2*)(g_qh + off) = hh;
                        *(__half2*)(g_ql + off) = hl;
                    } else if (three == 1) {
                        *(__half2*)(g_kf + off) = __floats2half2_rn(v.x, v.y);
                    } else {
                        *(__half2*)(g_vf + off) = __floats2half2_rn(v.x, v.y);
                    }
                } else {
                    v.x += bias[cg];
                    v.y += bias[cg + 1];
                    *(float2*)(out + (size_t)r * 1024 + cg) = v;
                }
            }
        }
    }
}

// ---------------------------------------------------------------------------
// mma.sync flash attention. Block = (bh, 64-query tile), 4 warps (16 rows each).
// S = (Qh+Ql)*K fp16 (2 passes), softmax in log2 domain (FMA-pipe exp2),
// O += P(fp16)*V(fp16). K/V double-buffered via cp.async.
// smem: Qs[64][136] | bias[64] | {K[64][72],V[64][72]} x2  = 54,528 B dynamic.
// ---------------------------------------------------------------------------
#define QSTR 136
#define KSTR 72
#define SM_KV0 17664
#define KVBUF  18432
#define ATTN_SMEM_BYTES 54528

__device__ __forceinline__ void stage_kv(uint32_t kd, const __half* ksrc,
                                         const __half* vsrc, int tid) {
#pragma unroll
    for (int t = 0; t < 4; t++) {
        int idx = tid + 128 * t;
        int r = idx >> 3, u = idx & 7;
        cp16(kd + (r * KSTR + u * 8) * 2, ksrc + r * 64 + u * 8);
        cp16(kd + 9216 + (r * KSTR + u * 8) * 2, vsrc + r * 64 + u * 8);
    }
}

__global__ __launch_bounds__(128) void attn_mma(const float* __restrict__ mWin) {
    extern __shared__ char smem[];
    __half* Qs = (__half*)smem;
    float* bias_s = (float*)(smem + 17408);

    const int tid = threadIdx.x;
    const int lane = tid & 31, w = tid >> 5;
    const int qt = blockIdx.x & 31;
    const int bh = blockIdx.x >> 5;
    const int b = bh >> 4, h = bh & 15;

    const __half* qh_g = g_qh + ((size_t)bh * 2048 + qt * 64) * 64;
    const __half* ql_g = g_ql + ((size_t)bh * 2048 + qt * 64) * 64;
    const __half* kf_g = g_kf + (size_t)bh * 2048 * 64;
    const __half* vf_g = g_vf + (size_t)bh * 2048 * 64;

    const uint32_t sbase = smem_u32(smem);

    // issue cp.async for key tile 0
    stage_kv(sbase + SM_KV0, kf_g, vf_g, tid);
    asm volatile("cp.async.commit_group;" ::: "memory");

    // stage Q ([Qh | Ql] rows of 128 halves)
#pragma unroll
    for (int t = 0; t < 8; t++) {
        int idx = tid + 128 * t;
        int r = idx >> 4, u = idx & 15;
        const __half* src = (u < 8) ? qh_g + r * 64 + u * 8
                                    : ql_g + r * 64 + (u - 8) * 8;
        *(uint4*)(smem + ((size_t)r * QSTR + u * 8) * 2) = *(const uint4*)src;
    }
    __syncthreads();

    // preload Q fragments (8 k-chunks x 4 regs)
    uint32_t aQ[8][4];
#pragma unroll
    for (int kc = 0; kc < 8; kc++) {
        uint32_t addr = sbase +
            ((w * 16 + (lane & 15)) * QSTR + kc * 16 + (lane >> 4) * 8) * 2;
        ldsm_x4(addr, aQ[kc][0], aQ[kc][1], aQ[kc][2], aQ[kc][3]);
    }

    // ldmatrix relative offsets
    uint32_t kb_rel[4], vb_rel[4];
#pragma unroll
    for (int p = 0; p < 4; p++)
        kb_rel[p] = ((p * 16 + ((lane >> 4) << 3) + (lane & 7)) * KSTR +
                     (((lane >> 3) & 1) << 3)) * 2;
#pragma unroll
    for (int dn = 0; dn < 4; dn++)
        vb_rel[dn] = ((((lane >> 3) & 1) * 8 + (lane & 7)) * KSTR +
                      dn * 16 + (lane >> 4) * 8) * 2;

    float accO[8][4] = {};
    float m_lo = -1e30f, m_hi = -1e30f, l_lo = 0.0f, l_hi = 0.0f;
    const int c2 = (lane & 3) * 2;

    for (int kt = 0; kt < 32; kt++) {
        const int buf = kt & 1;
        if (kt + 1 < 32) {
            stage_kv(sbase + SM_KV0 + (buf ^ 1) * KVBUF,
                     kf_g + (size_t)(kt + 1) * 64 * 64,
                     vf_g + (size_t)(kt + 1) * 64 * 64, tid);
            asm volatile("cp.async.commit_group;" ::: "memory");
            asm volatile("cp.async.wait_group 1;" ::: "memory");
        } else {
            asm volatile("cp.async.wait_group 0;" ::: "memory");
        }
        if (tid < 64)
            bias_s[tid] = (mWin[b * 2048 + kt * 64 + tid] * 100.0f - 100.0f) * LOG2E;
        __syncthreads();

        const uint32_t kbase = sbase + SM_KV0 + buf * KVBUF;
        const uint32_t vbase = kbase + 9216;

        // S = Qh*K + Ql*K
        float accS[8][4] = {};
#pragma unroll
        for (int dc = 0; dc < 4; dc++) {
#pragma unroll
            for (int p = 0; p < 4; p++) {
                uint32_t b0, b1, b2, b3;
                ldsm_x4(kbase + kb_rel[p] + dc * 32, b0, b1, b2, b3);
                uint32_t bb[2];
                bb[0] = b0; bb[1] = b1;
                mma_f16(accS[2 * p], aQ[dc], bb);
                mma_f16(accS[2 * p], aQ[dc + 4], bb);
                bb[0] = b2; bb[1] = b3;
                mma_f16(accS[2 * p + 1], aQ[dc], bb);
                mma_f16(accS[2 * p + 1], aQ[dc + 4], bb);
            }
        }

        // + key bias (log2 units)
#pragma unroll
        for (int j = 0; j < 8; j++) {
            float b0v = bias_s[8 * j + c2], b1v = bias_s[8 * j + c2 + 1];
            accS[j][0] += b0v; accS[j][1] += b1v;
            accS[j][2] += b0v; accS[j][3] += b1v;
        }

        // online softmax (rows r=lane>>2 and r+8)
        float mx0 = -1e30f, mx1 = -1e30f;
#pragma unroll
        for (int j = 0; j < 8; j++) {
            mx0 = fmaxf(mx0, fmaxf(accS[j][0], accS[j][1]));
            mx1 = fmaxf(mx1, fmaxf(accS[j][2], accS[j][3]));
        }
        mx0 = fmaxf(mx0, __shfl_xor_sync(0xffffffffu, mx0, 1));
        mx0 = fmaxf(mx0, __shfl_xor_sync(0xffffffffu, mx0, 2));
        mx1 = fmaxf(mx1, __shfl_xor_sync(0xffffffffu, mx1, 1));
        mx1 = fmaxf(mx1, __shfl_xor_sync(0xffffffffu, mx1, 2));
        float mn0 = fmaxf(m_lo, mx0), mn1 = fmaxf(m_hi, mx1);
        float cor0 = exp2_poly(m_lo - mn0), cor1 = exp2_poly(m_hi - mn1);
        m_lo = mn0; m_hi = mn1;

        float s0 = 0.0f, s1 = 0.0f;
#pragma unroll
        for (int j = 0; j < 8; j++) {
            accS[j][0] = exp2_poly(accS[j][0] - m_lo);
            accS[j][1] = exp2_poly(accS[j][1] - m_lo);
            accS[j][2] = exp2_poly(accS[j][2] - m_hi);
            accS[j][3] = exp2_poly(accS[j][3] - m_hi);
            s0 += accS[j][0] + accS[j][1];
            s1 += accS[j][2] + accS[j][3];
        }
        s0 += __shfl_xor_sync(0xffffffffu, s0, 1);
        s0 += __shfl_xor_sync(0xffffffffu, s0, 2);
        s1 += __shfl_xor_sync(0xffffffffu, s1, 1);
        s1 += __shfl_xor_sync(0xffffffffu, s1, 2);
        l_lo = l_lo * cor0 + s0;
        l_hi = l_hi * cor1 + s1;
#pragma unroll
        for (int j = 0; j < 8; j++) {
            accO[j][0] *= cor0; accO[j][1] *= cor0;
            accO[j][2] *= cor1; accO[j][3] *= cor1;
        }

        // pack P -> fp16 A-fragments (in registers)
        uint32_t ph[8][2];
#pragma unroll
        for (int j = 0; j < 8; j++) {
            ph[j][0] = pack_h2(accS[j][0], accS[j][1]);
            ph[j][1] = pack_h2(accS[j][2], accS[j][3]);
        }

        // O += P * V  (V via ldmatrix.trans)
#pragma unroll
        for (int kc = 0; kc < 4; kc++) {
            uint32_t a[4] = {ph[2 * kc][0], ph[2 * kc][1],
                             ph[2 * kc + 1][0], ph[2 * kc + 1][1]};
#pragma unroll
            for (int dn = 0; dn < 4; dn++) {
                uint32_t r0, r1, r2, r3;
                ldsm_x4_t(vbase + vb_rel[dn] + kc * 16 * KSTR * 2, r0, r1, r2, r3);
                uint32_t bb[2];
                bb[0] = r0; bb[1] = r1;
                mma_f16(accO[2 * dn], a, bb);
                bb[0] = r2; bb[1] = r3;
                mma_f16(accO[2 * dn + 1], a, bb);
            }
        }
        __syncthreads();
    }

    // epilogue: O / l -> g_ao[token][h*64+d]
    float i0 = 1.0f / l_lo, i1 = 1.0f / l_hi;
    int qn = qt * 64 + w * 16 + (lane >> 2);
    int col0 = h * 64 + c2;
#pragma unroll
    for (int j = 0; j < 8; j++) {
        *(float2*)&g_ao[(size_t)(b * 2048 + qn) * 1024 + col0 + 8 * j] =
            make_float2(accO[j][0] * i0, accO[j][1] * i0);
        *(float2*)&g_ao[(size_t)(b * 2048 + qn + 8) * 1024 + col0 + 8 * j] =
            make_float2(accO[j][2] * i1, accO[j][3] * i1);
    }
}

// ---------------------------------------------------------------------------
extern "C" void kernel_launch(void* const* d_in, const int* in_sizes, int n_in,
                              void* d_out, int out_size) {
    const float* x      = (const float*)d_in[0];
    const float* mWin   = (const float*)d_in[1];
    const float* w_qkv  = (const float*)d_in[2];
    const float* w_proj = (const float*)d_in[3];
    const float* b_proj = (const float*)d_in[4];
    float* out = (float*)d_out;

    __nv_bfloat16 *xhi, *xlo, *wqh, *wql, *wph, *wpl, *aoh, *aol;
    cudaGetSymbolAddress((void**)&xhi, g_xhi);
    cudaGetSymbolAddress((void**)&xlo, g_xlo);
    cudaGetSymbolAddress((void**)&wqh, g_wqh);
    cudaGetSymbolAddress((void**)&wql, g_wql);
    cudaGetSymbolAddress((void**)&wph, g_wph);
    cudaGetSymbolAddress((void**)&wpl, g_wpl);
    cudaGetSymbolAddress((void**)&aoh, g_aoh);
    cudaGetSymbolAddress((void**)&aol, g_aol);
    float* ao;
    cudaGetSymbolAddress((void**)&ao, g_ao);

    cudaFuncSetAttribute(attn_mma, cudaFuncAttributeMaxDynamicSharedMemorySize,
                         ATTN_SMEM_BYTES);

    // Split conversions (fp32 -> bf16 hi/lo)
    split_kernel<<<8192, 256>>>(x, xhi, xlo);
    split_kernel<<<3072, 256>>>(w_qkv, wqh, wql);
    split_kernel<<<1024, 256>>>(w_proj, wph, wpl);

    // QKV projection -> fp16 Qh/Ql (scaled), Kf, Vf
    gemm_mma<<<dim3(24, 64), 256>>>(xhi, xlo, wqh, wql, nullptr, nullptr, 0);

    // Flash attention (mma.sync fp16)
    attn_mma<<<2048, 128, ATTN_SMEM_BYTES>>>(mWin);

    // Output projection + bias
    split_kernel<<<8192, 256>>>(ao, aoh, aol);
    gemm_mma<<<dim3(8, 64), 256>>>(aoh, aol, wph, wpl, b_proj, out, 1);
}